// round 10
// baseline (speedup 1.0000x reference)
#include <cuda_runtime.h>

#define Bn 4
#define Cn 16
#define Kn 100
#define Pn 76800
#define ITERS 10
#define BW2F ((float)(0.16*0.16))

#define TPB 128
#define IPT 4                      // 4 points/thread
#define XB  (Pn/(TPB*IPT))         // 150
#define NB  (XB*Bn)                // 600 blocks = single wave @5/SM (<=740)
#define MSTR 20                    // floats per k: {-2m x16, mn2, 0, pad2}

typedef unsigned long long u64;

// ---- device scratch (static; no allocations) ----
__device__ float g_ms[ITERS+2][Bn*Kn*Cn];  // [0]=seeds, [it], [ITERS+1]=conv snapshot
__device__ float g_num[ITERS][Bn*Kn*Cn];
__device__ float g_den[ITERS][Bn*Kn];
__device__ int   g_bconv[Bn];
__device__ unsigned g_barcnt;

// ---- packed f32x2 helpers ----
__device__ __forceinline__ u64 pk2(float lo, float hi) {
    u64 r; asm("mov.b64 %0,{%1,%2};" : "=l"(r) : "f"(lo), "f"(hi)); return r;
}
__device__ __forceinline__ void up2(u64 v, float& lo, float& hi) {
    asm("mov.b64 {%0,%1},%2;" : "=f"(lo), "=f"(hi) : "l"(v));
}
__device__ __forceinline__ u64 f2fma(u64 a, u64 b, u64 c) {
    u64 d; asm("fma.rn.f32x2 %0,%1,%2,%3;" : "=l"(d) : "l"(a), "l"(b), "l"(c)); return d;
}
__device__ __forceinline__ u64 f2mul(u64 a, u64 b) {
    u64 d; asm("mul.rn.f32x2 %0,%1,%2;" : "=l"(d) : "l"(a), "l"(b)); return d;
}

// software grid barrier (all NB blocks co-resident by construction)
__device__ __forceinline__ void gridbar(int gen) {
    __syncthreads();
    if (threadIdx.x == 0) {
        __threadfence();                      // release prior writes
        atomicAdd(&g_barcnt, 1u);
        unsigned target = (unsigned)gen * (unsigned)NB;
        volatile unsigned* p = &g_barcnt;
        while (*p < target) __nanosleep(64);
        __threadfence();                      // acquire others' writes
    }
    __syncthreads();
}

// ---------------------------------------------------------------------------
// Init: reset barrier/conv, zero accumulators, detect idx width, gather seeds.
// ---------------------------------------------------------------------------
__global__ void init_kernel(const float* __restrict__ feat,
                            const void* __restrict__ idxraw) {
    __shared__ int s_is64;
    int tl = threadIdx.x;
    if (tl == 0) s_is64 = 1;
    __syncthreads();
    if (tl < 200) {   // first 1600 bytes valid under both layouts
        long long v = ((const long long*)idxraw)[tl];
        if (v < 0 || v >= (long long)Pn) s_is64 = 0;
    }
    __syncthreads();

    int t = blockIdx.x * blockDim.x + tl;
    int stride = gridDim.x * blockDim.x;
    if (t == 0) g_barcnt = 0u;
    if (t < Bn) g_bconv[t] = 0;
    float* num0 = &g_num[0][0];
    for (int i = t; i < ITERS * Bn * Kn * Cn; i += stride) num0[i] = 0.0f;
    float* den0 = &g_den[0][0];
    for (int i = t; i < ITERS * Bn * Kn; i += stride) den0[i] = 0.0f;

    if (t < Bn * Kn) {
        int b = t / Kn;
        long long idx = s_is64 ? ((const long long*)idxraw)[t]
                               : (long long)((const int*)idxraw)[t];
        const float* fb = feat + (size_t)b * Cn * Pn + (size_t)idx;
#pragma unroll
        for (int c = 0; c < Cn; c++)
            g_ms[0][t * Cn + c] = fb[(size_t)c * Pn];
    }
}

// single-chain shifted distance: s = mn2 + sum_c f_c * (-2 m_c)
__device__ __forceinline__ float dchain1(const u64 (&f)[8],
                                         ulonglong2 mA, ulonglong2 mB,
                                         ulonglong2 mC, ulonglong2 mD,
                                         u64 mnz) {
    u64 v = f2fma(f[0], mA.x, mnz);
    v = f2fma(f[1], mA.y, v);
    v = f2fma(f[2], mB.x, v);
    v = f2fma(f[3], mB.y, v);
    v = f2fma(f[4], mC.x, v);
    v = f2fma(f[5], mC.y, v);
    v = f2fma(f[6], mD.x, v);
    v = f2fma(f[7], mD.y, v);
    float lo, hi; up2(v, lo, hi);
    return lo + hi;
}

// rare slow path: rescan all Kn means for one point, exact hit atomics
__device__ __noinline__ void rescan(const u64 (&f)[8], float thr,
                                    const float* s_m, int b, int it) {
    for (int kl = 0; kl < Kn; kl++) {
        const ulonglong2* mp = (const ulonglong2*)&s_m[kl * MSTR];
        u64 mnz = *(const u64*)&s_m[kl * MSTR + 16];
        float s = dchain1(f, mp[0], mp[1], mp[2], mp[3], mnz);
        if (s < thr) {
            int kg = b * Kn + kl;
            atomicAdd(&g_den[it][kg], 1.0f);
#pragma unroll
            for (int j = 0; j < 8; j++) {
                float v0, v1; up2(f[j], v0, v1);
                atomicAdd(&g_num[it][kg * Cn + 2 * j],     v0);
                atomicAdd(&g_num[it][kg * Cn + 2 * j + 1], v1);
            }
        }
    }
}

// ---------------------------------------------------------------------------
// Persistent fused kernel: 10 accumulate passes + label pass, grid barriers
// between iterations, per-batch fixed-point latch skips dead scans.
// ---------------------------------------------------------------------------
__global__ void __launch_bounds__(TPB, 5)
fused_kernel(const float* __restrict__ feat, float* __restrict__ out,
             int out_size) {
    const int b = blockIdx.y;
    __shared__ __align__(16) float s_m[Kn * MSTR];
    __shared__ int s_cnt;

    // ---- load 4 consecutive points once; channel-packed pairs ----
    const int pbase = blockIdx.x * (TPB * IPT) + 4 * threadIdx.x;
    const float4* fb4 = (const float4*)(feat + (size_t)b * Cn * Pn + pbase);
    u64 f0[8], f1[8], f2[8], f3[8];
#pragma unroll
    for (int c = 0; c < Cn; c += 2) {
        float4 va = fb4[(size_t)c * (Pn / 4)];
        float4 vb = fb4[(size_t)(c + 1) * (Pn / 4)];
        f0[c / 2] = pk2(va.x, vb.x);
        f1[c / 2] = pk2(va.y, vb.y);
        f2[c / 2] = pk2(va.z, vb.z);
        f3[c / 2] = pk2(va.w, vb.w);
    }
    float fn2_0, fn2_1, fn2_2, fn2_3;
    {
        u64 q0 = f2mul(f0[0], f0[0]), q1 = f2mul(f1[0], f1[0]);
        u64 q2 = f2mul(f2[0], f2[0]), q3 = f2mul(f3[0], f3[0]);
#pragma unroll
        for (int j = 1; j < 8; j++) {
            q0 = f2fma(f0[j], f0[j], q0);
            q1 = f2fma(f1[j], f1[j], q1);
            q2 = f2fma(f2[j], f2[j], q2);
            q3 = f2fma(f3[j], f3[j], q3);
        }
        float lo, hi;
        up2(q0, lo, hi); fn2_0 = lo + hi;
        up2(q1, lo, hi); fn2_1 = lo + hi;
        up2(q2, lo, hi); fn2_2 = lo + hi;
        up2(q3, lo, hi); fn2_3 = lo + hi;
    }
    const float t0 = BW2F - fn2_0, t1 = BW2F - fn2_1;
    const float t2 = BW2F - fn2_2, t3 = BW2F - fn2_3;

    int gen = 0;
    for (int it = 0; it <= ITERS; it++) {
        const bool lab = (it == ITERS);
        const bool conv = (it > 0) && (g_bconv[b] != 0);

        if (!conv || lab) {
            // ---- prologue: build {-2m, mn2} table in smem ----
            if (threadIdx.x == 0) s_cnt = 0;
            __syncthreads();
            if (threadIdx.x < Kn) {
                int t = b * Kn + threadIdx.x;
                float mn2 = 0.0f;
                if (it == 0 || conv) {
                    const float* src = conv ? &g_ms[ITERS + 1][t * Cn]
                                            : &g_ms[0][t * Cn];
#pragma unroll
                    for (int c = 0; c < Cn; c++) {
                        float m = src[c];
                        s_m[threadIdx.x * MSTR + c] = -2.0f * m;
                        mn2 += m * m;
                    }
                } else {
                    float den = g_den[it - 1][t];
                    float dm = fmaxf(den, 1.0f);
                    bool pos = den > 0.0f;
                    bool same = true;
#pragma unroll
                    for (int c = 0; c < Cn; c++) {
                        float old = g_ms[it - 1][t * Cn + c];
                        float nm = pos ? (g_num[it - 1][t * Cn + c] / dm) : old;
                        s_m[threadIdx.x * MSTR + c] = -2.0f * nm;
                        mn2 += nm * nm;
                        same = same && (__float_as_uint(nm) == __float_as_uint(old));
                    }
                    if (same) atomicAdd(&s_cnt, 1);
                }
                s_m[threadIdx.x * MSTR + 16] = mn2;
                s_m[threadIdx.x * MSTR + 17] = 0.0f;
            }
            __syncthreads();

            bool do_scan = true;
            if (!lab && it > 0 && s_cnt == Kn) {
                // fixed point reached now: snapshot + latch, skip scan
                if (blockIdx.x == 0) {
                    for (int i = threadIdx.x; i < Kn * Cn; i += TPB)
                        g_ms[ITERS + 1][b * Kn * Cn + i] =
                            -0.5f * s_m[(i / Cn) * MSTR + (i % Cn)];
                    __threadfence();
                    if (threadIdx.x == 0) g_bconv[b] = 1;
                }
                do_scan = false;
            } else if (!lab && it > 0 && blockIdx.x == 0) {
                // persist means[it] for next prologue
                for (int i = threadIdx.x; i < Kn * Cn; i += TPB)
                    g_ms[it][b * Kn * Cn + i] =
                        -0.5f * s_m[(i / Cn) * MSTR + (i % Cn)];
            }

            if (do_scan) {
                float s0m = 3.4e38f, s1m = 3.4e38f, s2m = 3.4e38f, s3m = 3.4e38f;
                int i0 = 0, i1 = 0, i2 = 0, i3 = 0;
#pragma unroll 4
                for (int kl = 0; kl < Kn; kl++) {
                    const ulonglong2* mp = (const ulonglong2*)&s_m[kl * MSTR];
                    ulonglong2 mA = mp[0], mB = mp[1], mC = mp[2], mD = mp[3];
                    u64 mnz = *(const u64*)&s_m[kl * MSTR + 16];
                    float s0 = dchain1(f0, mA, mB, mC, mD, mnz);
                    float s1 = dchain1(f1, mA, mB, mC, mD, mnz);
                    float s2 = dchain1(f2, mA, mB, mC, mD, mnz);
                    float s3 = dchain1(f3, mA, mB, mC, mD, mnz);
                    if (!lab) {
                        s0m = fminf(s0m, s0);
                        s1m = fminf(s1m, s1);
                        s2m = fminf(s2m, s2);
                        s3m = fminf(s3m, s3);
                    } else {
                        if (s0 < s0m) { s0m = s0; i0 = kl; }
                        if (s1 < s1m) { s1m = s1; i1 = kl; }
                        if (s2 < s2m) { s2m = s2; i2 = kl; }
                        if (s3 < s3m) { s3m = s3; i3 = kl; }
                    }
                }
                if (!lab) {
                    if (s0m < t0) rescan(f0, t0, s_m, b, it);
                    if (s1m < t1) rescan(f1, t1, s_m, b, it);
                    if (s2m < t2) rescan(f2, t2, s_m, b, it);
                    if (s3m < t3) rescan(f3, t3, s_m, b, it);
                } else {
                    float* ob = out + (size_t)b * Pn + pbase;
                    ob[0] = (s0m < t0) ? (float)(i0 + 1) : 0.0f;
                    ob[1] = (s1m < t1) ? (float)(i1 + 1) : 0.0f;
                    ob[2] = (s2m < t2) ? (float)(i2 + 1) : 0.0f;
                    ob[3] = (s3m < t3) ? (float)(i3 + 1) : 0.0f;
                    if (blockIdx.x == 0) {
                        for (int i = threadIdx.x; i < Kn * Cn; i += TPB) {
                            int o = Bn * Pn + b * Kn * Cn + i;
                            if (o < out_size)
                                out[o] = -0.5f * s_m[(i / Cn) * MSTR + (i % Cn)];
                        }
                    }
                }
            }
        }

        if (!lab) gridbar(++gen);    // order scan[it] writes before prologue[it+1]
    }
}

extern "C" void kernel_launch(void* const* d_in, const int* in_sizes, int n_in,
                              void* d_out, int out_size) {
    const float* feat = (const float*)d_in[0];
    const void*  sidx = d_in[1];
    float* out = (float*)d_out;

    init_kernel<<<8, 1024>>>(feat, sidx);

    dim3 grid(XB, Bn);
    fused_kernel<<<grid, TPB>>>(feat, out, out_size);
}

// round 11
// speedup vs baseline: 1.3528x; 1.3528x over previous
#include <cuda_runtime.h>

#define Bn 4
#define Cn 16
#define Kn 100
#define Pn 76800
#define ITERS 10
#define BW2F ((float)(0.16*0.16))

#define TPB 128
#define IPT 4                      // 4 points/thread
#define XB  (Pn/(TPB*IPT))         // 150 blocks per batch
#define NB  (XB*Bn)                // 600 blocks = single wave @5/SM (<=740)
#define MSTR 20                    // floats per k: {-2m x16, mn2, 0, pad2}

typedef unsigned long long u64;

// ---- device scratch (static; no allocations) ----
__device__ float g_seed[Bn*Kn*Cn];
__device__ float g_num[ITERS][Bn*Kn*Cn];
__device__ float g_den[ITERS][Bn*Kn];
__device__ unsigned g_barcnt[Bn * 32];     // one counter per batch, padded

// ---- packed f32x2 helpers ----
__device__ __forceinline__ u64 pk2(float lo, float hi) {
    u64 r; asm("mov.b64 %0,{%1,%2};" : "=l"(r) : "f"(lo), "f"(hi)); return r;
}
__device__ __forceinline__ void up2(u64 v, float& lo, float& hi) {
    asm("mov.b64 {%0,%1},%2;" : "=f"(lo), "=f"(hi) : "l"(v));
}
__device__ __forceinline__ u64 f2fma(u64 a, u64 b, u64 c) {
    u64 d; asm("fma.rn.f32x2 %0,%1,%2,%3;" : "=l"(d) : "l"(a), "l"(b), "l"(c)); return d;
}
__device__ __forceinline__ u64 f2mul(u64 a, u64 b) {
    u64 d; asm("mul.rn.f32x2 %0,%1,%2;" : "=l"(d) : "l"(a), "l"(b)); return d;
}

// per-batch software barrier: only the XB blocks of one batch participate.
// All blocks of a batch execute the same deterministic control flow, so they
// arrive the same number of times before any of them stops participating.
__device__ __forceinline__ void batchbar(int b, int gen) {
    __syncthreads();
    if (threadIdx.x == 0) {
        __threadfence();                          // release scan[it] writes
        atomicAdd(&g_barcnt[b * 32], 1u);
        unsigned target = (unsigned)gen * (unsigned)XB;
        volatile unsigned* p = &g_barcnt[b * 32];
        while (*p < target) __nanosleep(32);
        __threadfence();                          // acquire others' writes
    }
    __syncthreads();
}

// ---------------------------------------------------------------------------
// Init: reset barriers, zero accumulators, detect idx width, gather seeds.
// ---------------------------------------------------------------------------
__global__ void init_kernel(const float* __restrict__ feat,
                            const void* __restrict__ idxraw) {
    __shared__ int s_is64;
    int tl = threadIdx.x;
    if (tl == 0) s_is64 = 1;
    __syncthreads();
    if (tl < 200) {   // first 1600 bytes valid under both layouts
        long long v = ((const long long*)idxraw)[tl];
        if (v < 0 || v >= (long long)Pn) s_is64 = 0;
    }
    __syncthreads();

    int t = blockIdx.x * blockDim.x + tl;
    int stride = gridDim.x * blockDim.x;
    if (t < Bn * 32) g_barcnt[t] = 0u;
    float* num0 = &g_num[0][0];
    for (int i = t; i < ITERS * Bn * Kn * Cn; i += stride) num0[i] = 0.0f;
    float* den0 = &g_den[0][0];
    for (int i = t; i < ITERS * Bn * Kn; i += stride) den0[i] = 0.0f;

    if (t < Bn * Kn) {
        int b = t / Kn;
        long long idx = s_is64 ? ((const long long*)idxraw)[t]
                               : (long long)((const int*)idxraw)[t];
        const float* fb = feat + (size_t)b * Cn * Pn + (size_t)idx;
#pragma unroll
        for (int c = 0; c < Cn; c++)
            g_seed[t * Cn + c] = fb[(size_t)c * Pn];
    }
}

// single-chain shifted distance: s = mn2 + sum_c f_c * (-2 m_c)
__device__ __forceinline__ float dchain1(const u64 (&f)[8],
                                         ulonglong2 mA, ulonglong2 mB,
                                         ulonglong2 mC, ulonglong2 mD,
                                         u64 mnz) {
    u64 v = f2fma(f[0], mA.x, mnz);
    v = f2fma(f[1], mA.y, v);
    v = f2fma(f[2], mB.x, v);
    v = f2fma(f[3], mB.y, v);
    v = f2fma(f[4], mC.x, v);
    v = f2fma(f[5], mC.y, v);
    v = f2fma(f[6], mD.x, v);
    v = f2fma(f[7], mD.y, v);
    float lo, hi; up2(v, lo, hi);
    return lo + hi;
}

// rare slow path: rescan all Kn means for one point, exact hit atomics
__device__ __noinline__ void rescan(const u64 (&f)[8], float thr,
                                    const float* s_m, int b, int it) {
    for (int kl = 0; kl < Kn; kl++) {
        const ulonglong2* mp = (const ulonglong2*)&s_m[kl * MSTR];
        u64 mnz = *(const u64*)&s_m[kl * MSTR + 16];
        float s = dchain1(f, mp[0], mp[1], mp[2], mp[3], mnz);
        if (s < thr) {
            int kg = b * Kn + kl;
            atomicAdd(&g_den[it][kg], 1.0f);
#pragma unroll
            for (int j = 0; j < 8; j++) {
                float v0, v1; up2(f[j], v0, v1);
                atomicAdd(&g_num[it][kg * Cn + 2 * j],     v0);
                atomicAdd(&g_num[it][kg * Cn + 2 * j + 1], v1);
            }
        }
    }
}

// ---------------------------------------------------------------------------
// Persistent fused kernel, per-batch pacing:
//   loop { accumulate scan[it]; batch barrier; prologue -> means[it+1];
//          if fixed-point: break }  then label pass with current s_m.
// ---------------------------------------------------------------------------
__global__ void __launch_bounds__(TPB, 5)
fused_kernel(const float* __restrict__ feat, float* __restrict__ out,
             int out_size) {
    const int b = blockIdx.y;
    __shared__ __align__(16) float s_m[Kn * MSTR];
    __shared__ int s_cnt;

    // ---- it=0 prologue: seeds -> {-2m, mn2} table ----
    if (threadIdx.x < Kn) {
        const float* src = &g_seed[(b * Kn + threadIdx.x) * Cn];
        float mn2 = 0.0f;
#pragma unroll
        for (int c = 0; c < Cn; c++) {
            float m = src[c];
            s_m[threadIdx.x * MSTR + c] = -2.0f * m;
            mn2 += m * m;
        }
        s_m[threadIdx.x * MSTR + 16] = mn2;
        s_m[threadIdx.x * MSTR + 17] = 0.0f;
    }

    // ---- load 4 consecutive points once; channel-packed pairs ----
    const int pbase = blockIdx.x * (TPB * IPT) + 4 * threadIdx.x;
    const float4* fb4 = (const float4*)(feat + (size_t)b * Cn * Pn + pbase);
    u64 f0[8], f1[8], f2[8], f3[8];
#pragma unroll
    for (int c = 0; c < Cn; c += 2) {
        float4 va = fb4[(size_t)c * (Pn / 4)];
        float4 vb = fb4[(size_t)(c + 1) * (Pn / 4)];
        f0[c / 2] = pk2(va.x, vb.x);
        f1[c / 2] = pk2(va.y, vb.y);
        f2[c / 2] = pk2(va.z, vb.z);
        f3[c / 2] = pk2(va.w, vb.w);
    }
    float fn2_0, fn2_1, fn2_2, fn2_3;
    {
        u64 q0 = f2mul(f0[0], f0[0]), q1 = f2mul(f1[0], f1[0]);
        u64 q2 = f2mul(f2[0], f2[0]), q3 = f2mul(f3[0], f3[0]);
#pragma unroll
        for (int j = 1; j < 8; j++) {
            q0 = f2fma(f0[j], f0[j], q0);
            q1 = f2fma(f1[j], f1[j], q1);
            q2 = f2fma(f2[j], f2[j], q2);
            q3 = f2fma(f3[j], f3[j], q3);
        }
        float lo, hi;
        up2(q0, lo, hi); fn2_0 = lo + hi;
        up2(q1, lo, hi); fn2_1 = lo + hi;
        up2(q2, lo, hi); fn2_2 = lo + hi;
        up2(q3, lo, hi); fn2_3 = lo + hi;
    }
    const float t0 = BW2F - fn2_0, t1 = BW2F - fn2_1;
    const float t2 = BW2F - fn2_2, t3 = BW2F - fn2_3;
    __syncthreads();

    // ---- accumulate iterations with fixed-point early exit ----
    int gen = 0;
    for (int it = 0; it < ITERS; it++) {
        // accumulate scan over current means
        {
            float s0m = 3.4e38f, s1m = 3.4e38f, s2m = 3.4e38f, s3m = 3.4e38f;
#pragma unroll 4
            for (int kl = 0; kl < Kn; kl++) {
                const ulonglong2* mp = (const ulonglong2*)&s_m[kl * MSTR];
                ulonglong2 mA = mp[0], mB = mp[1], mC = mp[2], mD = mp[3];
                u64 mnz = *(const u64*)&s_m[kl * MSTR + 16];
                s0m = fminf(s0m, dchain1(f0, mA, mB, mC, mD, mnz));
                s1m = fminf(s1m, dchain1(f1, mA, mB, mC, mD, mnz));
                s2m = fminf(s2m, dchain1(f2, mA, mB, mC, mD, mnz));
                s3m = fminf(s3m, dchain1(f3, mA, mB, mC, mD, mnz));
            }
            if (s0m < t0) rescan(f0, t0, s_m, b, it);
            if (s1m < t1) rescan(f1, t1, s_m, b, it);
            if (s2m < t2) rescan(f2, t2, s_m, b, it);
            if (s3m < t3) rescan(f3, t3, s_m, b, it);
        }

        batchbar(b, ++gen);   // scan[it] complete for this batch

        // prologue: means[it+1] from num/den[it]; old means recovered from s_m
        if (threadIdx.x == 0) s_cnt = 0;
        __syncthreads();
        if (threadIdx.x < Kn) {
            int t = b * Kn + threadIdx.x;
            float den = g_den[it][t];
            float dm = fmaxf(den, 1.0f);
            bool pos = den > 0.0f;
            bool same = true;
            float mn2 = 0.0f;
#pragma unroll
            for (int c = 0; c < Cn; c++) {
                float oldp = s_m[threadIdx.x * MSTR + c];       // -2*old (exact)
                float nm = pos ? (g_num[it][t * Cn + c] / dm) : (-0.5f * oldp);
                float np = -2.0f * nm;
                s_m[threadIdx.x * MSTR + c] = np;
                mn2 += nm * nm;
                same = same && (__float_as_uint(np) == __float_as_uint(oldp));
            }
            s_m[threadIdx.x * MSTR + 16] = mn2;
            if (same) atomicAdd(&s_cnt, 1);
        }
        __syncthreads();
        if (s_cnt == Kn) break;   // fixed point: all future scans are identical
    }

    // ---- label pass with converged/final means in s_m ----
    {
        float s0m = 3.4e38f, s1m = 3.4e38f, s2m = 3.4e38f, s3m = 3.4e38f;
        int i0 = 0, i1 = 0, i2 = 0, i3 = 0;
#pragma unroll 4
        for (int kl = 0; kl < Kn; kl++) {
            const ulonglong2* mp = (const ulonglong2*)&s_m[kl * MSTR];
            ulonglong2 mA = mp[0], mB = mp[1], mC = mp[2], mD = mp[3];
            u64 mnz = *(const u64*)&s_m[kl * MSTR + 16];
            float s0 = dchain1(f0, mA, mB, mC, mD, mnz);
            float s1 = dchain1(f1, mA, mB, mC, mD, mnz);
            float s2 = dchain1(f2, mA, mB, mC, mD, mnz);
            float s3 = dchain1(f3, mA, mB, mC, mD, mnz);
            if (s0 < s0m) { s0m = s0; i0 = kl; }
            if (s1 < s1m) { s1m = s1; i1 = kl; }
            if (s2 < s2m) { s2m = s2; i2 = kl; }
            if (s3 < s3m) { s3m = s3; i3 = kl; }
        }
        float* ob = out + (size_t)b * Pn + pbase;
        ob[0] = (s0m < t0) ? (float)(i0 + 1) : 0.0f;
        ob[1] = (s1m < t1) ? (float)(i1 + 1) : 0.0f;
        ob[2] = (s2m < t2) ? (float)(i2 + 1) : 0.0f;
        ob[3] = (s3m < t3) ? (float)(i3 + 1) : 0.0f;
        if (blockIdx.x == 0) {
            for (int i = threadIdx.x; i < Kn * Cn; i += TPB) {
                int o = Bn * Pn + b * Kn * Cn + i;
                if (o < out_size)
                    out[o] = -0.5f * s_m[(i / Cn) * MSTR + (i % Cn)];
            }
        }
    }
}

extern "C" void kernel_launch(void* const* d_in, const int* in_sizes, int n_in,
                              void* d_out, int out_size) {
    const float* feat = (const float*)d_in[0];
    const void*  sidx = d_in[1];
    float* out = (float*)d_out;

    init_kernel<<<8, 1024>>>(feat, sidx);

    dim3 grid(XB, Bn);
    fused_kernel<<<grid, TPB>>>(feat, out, out_size);
}

// round 12
// speedup vs baseline: 1.6520x; 1.2212x over previous
#include <cuda_runtime.h>

#define Bn 4
#define Cn 16
#define Kn 100
#define Pn 76800
#define ITERS 10
#define BW2F ((float)(0.16*0.16))

#define TPB 128
#define IPT 4                      // 4 points/thread
#define XB  (Pn/(TPB*IPT))         // 150 blocks per batch
#define MSTR 20                    // floats per k: {-2m x16, mn2, 0, pad2}

typedef unsigned long long u64;

// ---- device scratch (static; no allocations) ----
__device__ float g_seed[Bn*Kn*Cn];
__device__ float g_num[ITERS][Bn*Kn*Cn];
__device__ float g_den[ITERS][Bn*Kn];
__device__ unsigned g_barcnt[Bn * 32];     // one counter per batch, padded

// ---- packed f32x2 helpers ----
__device__ __forceinline__ u64 pk2(float lo, float hi) {
    u64 r; asm("mov.b64 %0,{%1,%2};" : "=l"(r) : "f"(lo), "f"(hi)); return r;
}
__device__ __forceinline__ void up2(u64 v, float& lo, float& hi) {
    asm("mov.b64 {%0,%1},%2;" : "=f"(lo), "=f"(hi) : "l"(v));
}
__device__ __forceinline__ u64 f2fma(u64 a, u64 b, u64 c) {
    u64 d; asm("fma.rn.f32x2 %0,%1,%2,%3;" : "=l"(d) : "l"(a), "l"(b), "l"(c)); return d;
}
__device__ __forceinline__ u64 f2mul(u64 a, u64 b) {
    u64 d; asm("mul.rn.f32x2 %0,%1,%2;" : "=l"(d) : "l"(a), "l"(b)); return d;
}

// per-batch software barrier: only the XB blocks of one batch participate.
// All blocks of a batch run the same deterministic control flow -> same
// arrival counts.
__device__ __forceinline__ void batchbar(int b, int gen) {
    __syncthreads();
    if (threadIdx.x == 0) {
        __threadfence();                          // release scan[it] writes
        atomicAdd(&g_barcnt[b * 32], 1u);
        unsigned target = (unsigned)gen * (unsigned)XB;
        volatile unsigned* p = &g_barcnt[b * 32];
        while (*p < target) __nanosleep(32);
        __threadfence();                          // acquire others' writes
    }
    __syncthreads();
}

// ---------------------------------------------------------------------------
// Init: reset barriers, zero accumulators, detect idx width, gather seeds.
// ---------------------------------------------------------------------------
__global__ void init_kernel(const float* __restrict__ feat,
                            const void* __restrict__ idxraw) {
    __shared__ int s_is64;
    int tl = threadIdx.x;
    if (tl == 0) s_is64 = 1;
    __syncthreads();
    if (tl < 200) {   // first 1600 bytes valid under both layouts
        long long v = ((const long long*)idxraw)[tl];
        if (v < 0 || v >= (long long)Pn) s_is64 = 0;
    }
    __syncthreads();

    int t = blockIdx.x * blockDim.x + tl;
    int stride = gridDim.x * blockDim.x;
    if (t < Bn * 32) g_barcnt[t] = 0u;
    float* num0 = &g_num[0][0];
    for (int i = t; i < ITERS * Bn * Kn * Cn; i += stride) num0[i] = 0.0f;
    float* den0 = &g_den[0][0];
    for (int i = t; i < ITERS * Bn * Kn; i += stride) den0[i] = 0.0f;

    if (t < Bn * Kn) {
        int b = t / Kn;
        long long idx = s_is64 ? ((const long long*)idxraw)[t]
                               : (long long)((const int*)idxraw)[t];
        const float* fb = feat + (size_t)b * Cn * Pn + (size_t)idx;
#pragma unroll
        for (int c = 0; c < Cn; c++)
            g_seed[t * Cn + c] = fb[(size_t)c * Pn];
    }
}

// single-chain shifted distance: s = mn2 + sum_c f_c * (-2 m_c)
__device__ __forceinline__ float dchain1(const u64 (&f)[8],
                                         ulonglong2 mA, ulonglong2 mB,
                                         ulonglong2 mC, ulonglong2 mD,
                                         u64 mnz) {
    u64 v = f2fma(f[0], mA.x, mnz);
    v = f2fma(f[1], mA.y, v);
    v = f2fma(f[2], mB.x, v);
    v = f2fma(f[3], mB.y, v);
    v = f2fma(f[4], mC.x, v);
    v = f2fma(f[5], mC.y, v);
    v = f2fma(f[6], mD.x, v);
    v = f2fma(f[7], mD.y, v);
    float lo, hi; up2(v, lo, hi);
    return lo + hi;
}

// rare slow path: rescan all Kn means for one point, exact hit atomics
__device__ __noinline__ void rescan(const u64 (&f)[8], float thr,
                                    const float* s_m, int b, int it) {
    for (int kl = 0; kl < Kn; kl++) {
        const ulonglong2* mp = (const ulonglong2*)&s_m[kl * MSTR];
        u64 mnz = *(const u64*)&s_m[kl * MSTR + 16];
        float s = dchain1(f, mp[0], mp[1], mp[2], mp[3], mnz);
        if (s < thr) {
            int kg = b * Kn + kl;
            atomicAdd(&g_den[it][kg], 1.0f);
#pragma unroll
            for (int j = 0; j < 8; j++) {
                float v0, v1; up2(f[j], v0, v1);
                atomicAdd(&g_num[it][kg * Cn + 2 * j],     v0);
                atomicAdd(&g_num[it][kg * Cn + 2 * j + 1], v1);
            }
        }
    }
}

// ---------------------------------------------------------------------------
// Persistent fused kernel. Accumulate scans track (min, argmin); on a bitwise
// fixed point the last scan's results ARE the label results (final means ==
// means used by that scan), so the label pass is skipped. Fallback label scan
// only if 10 iterations complete without convergence.
// ---------------------------------------------------------------------------
__global__ void __launch_bounds__(TPB, 5)
fused_kernel(const float* __restrict__ feat, float* __restrict__ out,
             int out_size) {
    const int b = blockIdx.y;
    __shared__ __align__(16) float s_m[Kn * MSTR];
    __shared__ int s_cnt;

    // ---- it=0 prologue: seeds -> {-2m, mn2} table ----
    if (threadIdx.x < Kn) {
        const float* src = &g_seed[(b * Kn + threadIdx.x) * Cn];
        float mn2 = 0.0f;
#pragma unroll
        for (int c = 0; c < Cn; c++) {
            float m = src[c];
            s_m[threadIdx.x * MSTR + c] = -2.0f * m;
            mn2 += m * m;
        }
        s_m[threadIdx.x * MSTR + 16] = mn2;
        s_m[threadIdx.x * MSTR + 17] = 0.0f;
    }

    // ---- load 4 consecutive points once; channel-packed pairs ----
    const int pbase = blockIdx.x * (TPB * IPT) + 4 * threadIdx.x;
    const float4* fb4 = (const float4*)(feat + (size_t)b * Cn * Pn + pbase);
    u64 f0[8], f1[8], f2[8], f3[8];
#pragma unroll
    for (int c = 0; c < Cn; c += 2) {
        float4 va = fb4[(size_t)c * (Pn / 4)];
        float4 vb = fb4[(size_t)(c + 1) * (Pn / 4)];
        f0[c / 2] = pk2(va.x, vb.x);
        f1[c / 2] = pk2(va.y, vb.y);
        f2[c / 2] = pk2(va.z, vb.z);
        f3[c / 2] = pk2(va.w, vb.w);
    }
    float fn2_0, fn2_1, fn2_2, fn2_3;
    {
        u64 q0 = f2mul(f0[0], f0[0]), q1 = f2mul(f1[0], f1[0]);
        u64 q2 = f2mul(f2[0], f2[0]), q3 = f2mul(f3[0], f3[0]);
#pragma unroll
        for (int j = 1; j < 8; j++) {
            q0 = f2fma(f0[j], f0[j], q0);
            q1 = f2fma(f1[j], f1[j], q1);
            q2 = f2fma(f2[j], f2[j], q2);
            q3 = f2fma(f3[j], f3[j], q3);
        }
        float lo, hi;
        up2(q0, lo, hi); fn2_0 = lo + hi;
        up2(q1, lo, hi); fn2_1 = lo + hi;
        up2(q2, lo, hi); fn2_2 = lo + hi;
        up2(q3, lo, hi); fn2_3 = lo + hi;
    }
    const float t0 = BW2F - fn2_0, t1 = BW2F - fn2_1;
    const float t2 = BW2F - fn2_2, t3 = BW2F - fn2_3;
    __syncthreads();

    // label state (filled by whichever scan ends up being final)
    float s0m, s1m, s2m, s3m;
    int i0, i1, i2, i3;
    bool done = false;

    // ---- accumulate iterations with fixed-point early exit ----
    int gen = 0;
    for (int it = 0; it < ITERS; it++) {
        // scan with (min, argmin) tracking
        s0m = 3.4e38f; s1m = 3.4e38f; s2m = 3.4e38f; s3m = 3.4e38f;
        i0 = 0; i1 = 0; i2 = 0; i3 = 0;
#pragma unroll 4
        for (int kl = 0; kl < Kn; kl++) {
            const ulonglong2* mp = (const ulonglong2*)&s_m[kl * MSTR];
            ulonglong2 mA = mp[0], mB = mp[1], mC = mp[2], mD = mp[3];
            u64 mnz = *(const u64*)&s_m[kl * MSTR + 16];
            float s0 = dchain1(f0, mA, mB, mC, mD, mnz);
            float s1 = dchain1(f1, mA, mB, mC, mD, mnz);
            float s2 = dchain1(f2, mA, mB, mC, mD, mnz);
            float s3 = dchain1(f3, mA, mB, mC, mD, mnz);
            if (s0 < s0m) { s0m = s0; i0 = kl; }
            if (s1 < s1m) { s1m = s1; i1 = kl; }
            if (s2 < s2m) { s2m = s2; i2 = kl; }
            if (s3 < s3m) { s3m = s3; i3 = kl; }
        }
        if (s0m < t0) rescan(f0, t0, s_m, b, it);
        if (s1m < t1) rescan(f1, t1, s_m, b, it);
        if (s2m < t2) rescan(f2, t2, s_m, b, it);
        if (s3m < t3) rescan(f3, t3, s_m, b, it);

        batchbar(b, ++gen);   // scan[it] complete for this batch

        // prologue: means[it+1] from num/den[it]; old recovered from s_m
        if (threadIdx.x == 0) s_cnt = 0;
        __syncthreads();
        if (threadIdx.x < Kn) {
            int t = b * Kn + threadIdx.x;
            float den = g_den[it][t];
            float dm = fmaxf(den, 1.0f);
            bool pos = den > 0.0f;
            bool same = true;
            float mn2 = 0.0f;
#pragma unroll
            for (int c = 0; c < Cn; c++) {
                float oldp = s_m[threadIdx.x * MSTR + c];       // -2*old (exact)
                float nm = pos ? (g_num[it][t * Cn + c] / dm) : (-0.5f * oldp);
                float np = -2.0f * nm;
                s_m[threadIdx.x * MSTR + c] = np;
                mn2 += nm * nm;
                same = same && (__float_as_uint(np) == __float_as_uint(oldp));
            }
            s_m[threadIdx.x * MSTR + 16] = mn2;
            if (same) atomicAdd(&s_cnt, 1);
        }
        __syncthreads();
        if (s_cnt == Kn) { done = true; break; }  // final means == means[it]:
                                                  // last scan == label scan
    }

    // ---- fallback label scan (only if not converged in 10 iters) ----
    if (!done) {
        s0m = 3.4e38f; s1m = 3.4e38f; s2m = 3.4e38f; s3m = 3.4e38f;
        i0 = 0; i1 = 0; i2 = 0; i3 = 0;
#pragma unroll 4
        for (int kl = 0; kl < Kn; kl++) {
            const ulonglong2* mp = (const ulonglong2*)&s_m[kl * MSTR];
            ulonglong2 mA = mp[0], mB = mp[1], mC = mp[2], mD = mp[3];
            u64 mnz = *(const u64*)&s_m[kl * MSTR + 16];
            float s0 = dchain1(f0, mA, mB, mC, mD, mnz);
            float s1 = dchain1(f1, mA, mB, mC, mD, mnz);
            float s2 = dchain1(f2, mA, mB, mC, mD, mnz);
            float s3 = dchain1(f3, mA, mB, mC, mD, mnz);
            if (s0 < s0m) { s0m = s0; i0 = kl; }
            if (s1 < s1m) { s1m = s1; i1 = kl; }
            if (s2 < s2m) { s2m = s2; i2 = kl; }
            if (s3 < s3m) { s3m = s3; i3 = kl; }
        }
    }

    // ---- emit labels + means tail ----
    float* ob = out + (size_t)b * Pn + pbase;
    ob[0] = (s0m < t0) ? (float)(i0 + 1) : 0.0f;
    ob[1] = (s1m < t1) ? (float)(i1 + 1) : 0.0f;
    ob[2] = (s2m < t2) ? (float)(i2 + 1) : 0.0f;
    ob[3] = (s3m < t3) ? (float)(i3 + 1) : 0.0f;
    if (blockIdx.x == 0) {
        for (int i = threadIdx.x; i < Kn * Cn; i += TPB) {
            int o = Bn * Pn + b * Kn * Cn + i;
            if (o < out_size)
                out[o] = -0.5f * s_m[(i / Cn) * MSTR + (i % Cn)];
        }
    }
}

extern "C" void kernel_launch(void* const* d_in, const int* in_sizes, int n_in,
                              void* d_out, int out_size) {
    const float* feat = (const float*)d_in[0];
    const void*  sidx = d_in[1];
    float* out = (float*)d_out;

    init_kernel<<<8, 1024>>>(feat, sidx);

    dim3 grid(XB, Bn);
    fused_kernel<<<grid, TPB>>>(feat, out, out_size);
}